// round 15
// baseline (speedup 1.0000x reference)
#include <cuda_runtime.h>
#include <cuda_fp16.h>
#include <math.h>
#include <stdint.h>

#define T_FRAMES 64
#define SPIRAL_S 9

// -------------------- static device scratch (no allocations) --------------------
__device__ __half g_bufA[10287104];  // conv/dense outputs (fp16)
__device__ __half g_bufB[20574208];  // pooled tensors (fp16)
__device__ float  g_WT[277344];      // packed weights: fp16 frag images (l<4), final fp32
__device__ int    g_ptr[6680];       // CSR row pointers
__device__ int    g_eid[20016];      // CSR entry ids
__device__ int    g_ccol[20016];     // CSR cols
__device__ float  g_cval[20016];     // CSR vals

#define WT_FINAL_F32_OFF 138240

struct CsrDesc {
    const int*   rows[4];
    const int*   cols[4];
    const float* vals[4];
    int nnz[4];
    int nnzOff[5];
    int nout[4];
    int ptrOff[4];
};

struct TDesc {
    const float* W[5];
    int K[5];
    int C[5];
    int offH[5];
    int tot;
};

// -------------------- fused prologue: CSR (blocks 0-3) + dense (4-163) + pack (164+) ------
#define PRO_DENSE_BLKS 160
#define PRO_PACK_BLKS  40
#define PRO_TOTAL_BLKS (4 + PRO_DENSE_BLKS + PRO_PACK_BLKS)

__global__ void __launch_bounds__(1024)
fused_prologue(CsrDesc cd, int* __restrict__ ptr, int* __restrict__ eid,
               int* __restrict__ ccol, float* __restrict__ cval,
               const float* __restrict__ latent, const float* __restrict__ W0,
               const float* __restrict__ b0, __half* __restrict__ dout,
               TDesc td, float* __restrict__ WT) {
    __shared__ int cnt[5024];
    __shared__ int sptr[5024];
    __shared__ int ssum[1024];

    int bid = blockIdx.x;
    int tid = threadIdx.x;

    if (bid < 4) {
        int l = bid;
        int n = cd.nout[l];
        int nnz = cd.nnz[l];
        int nb = cd.nnzOff[l];
        int pbase = cd.ptrOff[l];
        const int* rows = cd.rows[l];

        for (int i = tid; i <= n; i += 1024) cnt[i] = 0;
        __syncthreads();
        for (int e = tid; e < nnz; e += 1024) atomicAdd(&cnt[rows[e]], 1);
        __syncthreads();

        int v[5], loc[5];
        int s = 0;
#pragma unroll
        for (int j = 0; j < 5; j++) {
            int idx = tid * 5 + j;
            loc[j] = s;
            v[j] = (idx < n) ? cnt[idx] : 0;
            s += v[j];
        }
        ssum[tid] = s;
        __syncthreads();
        for (int off = 1; off < 1024; off <<= 1) {
            int t = (tid >= off) ? ssum[tid - off] : 0;
            __syncthreads();
            ssum[tid] += t;
            __syncthreads();
        }
        int ex = (tid > 0) ? ssum[tid - 1] : 0;
#pragma unroll
        for (int j = 0; j < 5; j++) {
            int idx = tid * 5 + j;
            if (idx < n) sptr[idx] = nb + ex + loc[j];
        }
        if (tid == 0) sptr[n] = nb + nnz;
        __syncthreads();

        for (int i = tid; i <= n; i += 1024) cnt[i] = 0;
        __syncthreads();
        for (int e = tid; e < nnz; e += 1024) {
            int r = rows[e];
            int pos = sptr[r] + atomicAdd(&cnt[r], 1);
            eid[pos] = e;
        }
        __syncthreads();

        const int* cols = cd.cols[l];
        const float* vals = cd.vals[l];
        for (int r = tid; r < n; r += 1024) {
            int j0 = sptr[r], j1 = sptr[r + 1];
            for (int a = j0 + 1; a < j1; a++) {
                int key = eid[a];
                int b = a - 1;
                while (b >= j0 && eid[b] > key) { eid[b + 1] = eid[b]; b--; }
                eid[b + 1] = key;
            }
            for (int j = j0; j < j1; j++) {
                int e = eid[j];
                ccol[j] = cols[e];
                cval[j] = vals[e];
            }
        }
        for (int i = tid; i <= n; i += 1024) ptr[pbase + i] = sptr[i];
    } else if (bid < 4 + PRO_DENSE_BLKS) {
        int warp = tid >> 5;
        int lane = tid & 31;
        int gw = (bid - 4) * 32 + warp;
        for (int o = gw; o < 64 * 2560; o += PRO_DENSE_BLKS * 32) {
            int t = o / 2560;
            int j = o - t * 2560;
            const float* lrow = latent + t * 128;
            const float* wrow = W0 + (size_t)j * 128;
            float acc = 0.f;
#pragma unroll
            for (int k = lane; k < 128; k += 32) acc += lrow[k] * wrow[k];
#pragma unroll
            for (int off = 16; off > 0; off >>= 1) acc += __shfl_down_sync(0xffffffffu, acc, off);
            if (lane == 0) dout[(size_t)t * 2560 + j] = __float2half(acc + b0[j]);
        }
    } else {
        __half* WH = (__half*)WT;
        int i = (bid - 4 - PRO_DENSE_BLKS) * 1024 + tid;
        int st = PRO_PACK_BLKS * 1024;
        for (; i < td.tot; i += st) {
            int l = 0, o = i;
            while (l < 4 && o >= td.K[l] * td.C[l]) { o -= td.K[l] * td.C[l]; l++; }
            int K = td.K[l], C = td.C[l];
            int k = o / C;
            int c = o - k * C;
            float v = td.W[l][(size_t)c * K + k];
            if (l < 4) {
                int kc = k >> 4;
                int kk = k & 15;
                int nt = c >> 3;
                int lane2 = (c & 7) * 4 + ((kk >> 1) & 3);
                int reg = kk >> 3;
                int h = kk & 1;
                int idx32 = (kc * (C >> 3) + nt) * 64 + lane2 * 2 + reg;
                WH[td.offH[l] + idx32 * 2 + h] = __float2half(v);
            } else {
                WT[WT_FINAL_F32_OFF + o] = v;
            }
        }
    }
}

// -------------------- gather pool: fp16->fp16, grid (n_out, 64/TCH), 128 threads ----------
template <int C, int TCH>
__global__ void __launch_bounds__(128)
pool_gather(const __half* __restrict__ x, __half* __restrict__ out,
            const int* __restrict__ ptr, const int* __restrict__ ccol,
            const float* __restrict__ cval, int n_in, int n_out) {
    constexpr int CH = C / 2;
    constexpr int TGI = 128 / CH;
    constexpr int TPG = TCH / TGI;
    static_assert(TPG >= 4 && TPG % 4 == 0, "TPG must be multiple of 4");
    int r = blockIdx.x;
    int tb = blockIdx.y * TCH;
    int tid = threadIdx.x;
    int c2 = tid % CH;
    int tg = tid / CH;
    int j0 = ptr[r], j1 = ptr[r + 1];
    int deg = j1 - j0;
    __shared__ int scol[32];
    __shared__ float sval[32];
    int dm = deg < 32 ? deg : 32;
    if (tid < dm) { scol[tid] = ccol[j0 + tid]; sval[tid] = cval[j0 + tid]; }
    __syncthreads();
    size_t sx = (size_t)n_in * CH;
    size_t so = (size_t)n_out * CH;
    const __half2* x2 = (const __half2*)x;
    __half2* o2 = (__half2*)out;
    int t0 = tb + tg * TPG;
    for (int t = t0; t < t0 + TPG; t += 4) {
        float2 a0 = make_float2(0.f, 0.f), a1 = a0, a2 = a0, a3 = a0;
        for (int j = 0; j < dm; j++) {
            float v = sval[j];
            size_t base = ((size_t)t * n_in + scol[j]) * CH + c2;
            float2 f0 = __half22float2(x2[base]);
            float2 f1 = __half22float2(x2[base + sx]);
            float2 f2 = __half22float2(x2[base + 2 * sx]);
            float2 f3 = __half22float2(x2[base + 3 * sx]);
            a0.x += v * f0.x; a0.y += v * f0.y;
            a1.x += v * f1.x; a1.y += v * f1.y;
            a2.x += v * f2.x; a2.y += v * f2.y;
            a3.x += v * f3.x; a3.y += v * f3.y;
        }
        for (int j = 32; j < deg; j++) {
            float v = cval[j0 + j];
            size_t base = ((size_t)t * n_in + ccol[j0 + j]) * CH + c2;
            float2 f0 = __half22float2(x2[base]);
            float2 f1 = __half22float2(x2[base + sx]);
            float2 f2 = __half22float2(x2[base + 2 * sx]);
            float2 f3 = __half22float2(x2[base + 3 * sx]);
            a0.x += v * f0.x; a0.y += v * f0.y;
            a1.x += v * f1.x; a1.y += v * f1.y;
            a2.x += v * f2.x; a2.y += v * f2.y;
            a3.x += v * f3.x; a3.y += v * f3.y;
        }
        size_t ob = ((size_t)t * n_out + r) * CH + c2;
        o2[ob] = __floats2half2_rn(a0.x, a0.y);
        o2[ob + so] = __floats2half2_rn(a1.x, a1.y);
        o2[ob + 2 * so] = __floats2half2_rn(a2.x, a2.y);
        o2[ob + 3 * so] = __floats2half2_rn(a3.x, a3.y);
    }
}

// -------------------- spiral conv: fp16 mma + ldmatrix + 2-stage cp.async (R13) ----------
template <int CIN, int COUT, int CON>
__global__ void __launch_bounds__(128)
conv_fp16(const __half* __restrict__ x, const int* __restrict__ spiral,
          const uint2* __restrict__ Bpk, const float* __restrict__ bias,
          __half* __restrict__ out, int nverts) {
    constexpr int K   = SPIRAL_S * CIN;
    constexpr int NCH = K / 32;
    constexpr int NT  = CON / 8;
    constexpr int NTILES = COUT / 8;

    __shared__ __align__(16) __half xg[2][128 * 40];
    __shared__ int vidx[2 * SPIRAL_S];

    int tid = threadIdx.x;
    int warp = tid >> 5;
    int lane = tid & 31;
    int n0 = blockIdx.x * 2;
    int co0 = blockIdx.z * CON;
    int nt0 = co0 >> 3;

    if (tid < 2 * SPIRAL_S) {
        int v = n0 + tid / SPIRAL_S;
        if (v >= nverts) v = nverts - 1;
        vidx[tid] = spiral[v * SPIRAL_S + tid % SPIRAL_S];
    }
    __syncthreads();

    float acc[2][NT][4];
#pragma unroll
    for (int mt = 0; mt < 2; mt++)
#pragma unroll
        for (int nt = 0; nt < NT; nt++)
#pragma unroll
            for (int j = 0; j < 4; j++) acc[mt][nt][j] = 0.f;

    auto fill_async = [&](int c, int b) {
        int s = (c * 32) / CIN;
        int ci0 = (c * 32) % CIN;
#pragma unroll
        for (int i = tid; i < 1024; i += 128) {
            int row = i >> 3;
            int c8 = i & 7;
            int v = row >> 6;
            int t = row & 63;
            const void* g = &x[((size_t)t * nverts + vidx[v * SPIRAL_S + s]) * CIN + ci0 + c8 * 4];
            uint32_t d = (uint32_t)__cvta_generic_to_shared(&xg[b][row * 40 + c8 * 4]);
            asm volatile("cp.async.ca.shared.global [%0], [%1], 8;" :: "r"(d), "l"(g));
        }
    };

    fill_async(0, 0);
    asm volatile("cp.async.commit_group;" ::: "memory");

    int rbase = warp * 32;
    int lm_row = (lane & 7) + ((lane >> 3) & 1) * 8;
    int lm_col = (lane >> 4) * 8;

    for (int c = 0; c < NCH; c++) {
        __syncthreads();
        if (c + 1 < NCH) {
            fill_async(c + 1, (c + 1) & 1);
            asm volatile("cp.async.commit_group;" ::: "memory");
            asm volatile("cp.async.wait_group 1;" ::: "memory");
        } else {
            asm volatile("cp.async.wait_group 0;" ::: "memory");
        }
        __syncthreads();
        const __half* xb = xg[c & 1];
#pragma unroll
        for (int j = 0; j < 2; j++) {
            uint32_t a[2][4];
#pragma unroll
            for (int mt = 0; mt < 2; mt++) {
                uint32_t ad = (uint32_t)__cvta_generic_to_shared(
                    &xb[(rbase + mt * 16 + lm_row) * 40 + j * 16 + lm_col]);
                asm volatile(
                    "ldmatrix.sync.aligned.m8n8.x4.shared.b16 {%0,%1,%2,%3}, [%4];"
                    : "=r"(a[mt][0]), "=r"(a[mt][1]), "=r"(a[mt][2]), "=r"(a[mt][3])
                    : "r"(ad));
            }
            int kc = c * 2 + j;
            const uint2* bp = Bpk + (size_t)(kc * NTILES + nt0) * 32 + lane;
#pragma unroll
            for (int nt = 0; nt < NT; nt++) {
                uint2 bb = bp[nt * 32];
#pragma unroll
                for (int mt = 0; mt < 2; mt++) {
                    asm volatile(
                        "mma.sync.aligned.m16n8k16.row.col.f32.f16.f16.f32 "
                        "{%0,%1,%2,%3}, {%4,%5,%6,%7}, {%8,%9}, {%0,%1,%2,%3};"
                        : "+f"(acc[mt][nt][0]), "+f"(acc[mt][nt][1]),
                          "+f"(acc[mt][nt][2]), "+f"(acc[mt][nt][3])
                        : "r"(a[mt][0]), "r"(a[mt][1]), "r"(a[mt][2]), "r"(a[mt][3]),
                          "r"(bb.x), "r"(bb.y));
                }
            }
        }
    }

#pragma unroll
    for (int mt = 0; mt < 2; mt++) {
        int row0 = rbase + mt * 16 + (lane >> 2);
#pragma unroll
        for (int hf = 0; hf < 2; hf++) {
            int row = row0 + hf * 8;
            int v = row >> 6;
            int t = row & 63;
            int n = n0 + v;
            if (n >= nverts) continue;
#pragma unroll
            for (int nt = 0; nt < NT; nt++) {
                int co = co0 + nt * 8 + (lane & 3) * 2;
                float2 bv = *(const float2*)&bias[co];
                float v0 = acc[mt][nt][hf * 2 + 0] + bv.x;
                float v1 = acc[mt][nt][hf * 2 + 1] + bv.y;
                v0 = (v0 > 0.f) ? v0 : (__expf(v0) - 1.f);
                v1 = (v1 > 0.f) ? v1 : (__expf(v1) - 1.f);
                *(__half2*)&out[((size_t)t * nverts + n) * COUT + co] = __floats2half2_rn(v0, v1);
            }
        }
    }
}

// ---- final conv 32->3 + actor: 2 vertices/block, cp.async double-buffered ----
__global__ void __launch_bounds__(128)
final_kernel(const __half* __restrict__ x, const int* __restrict__ spiral,
             const float* __restrict__ WTf,  // [288][3]
             const float* __restrict__ bf,
             const float* __restrict__ actor,
             float* __restrict__ out, int nverts) {
    __shared__ float wfs[864];
    __shared__ __align__(8) __half xg[2][2 * 64 * 34];  // [buf][v*64*34 + t*34 + ch]
    __shared__ int vidx[2 * SPIRAL_S];
    int n0 = blockIdx.x * 2;
    int tid = threadIdx.x;
    for (int i = tid; i < 864; i += 128) wfs[i] = WTf[i];
    if (tid < 2 * SPIRAL_S) {
        int v = n0 + tid / SPIRAL_S;
        if (v >= nverts) v = nverts - 1;
        vidx[tid] = spiral[v * SPIRAL_S + tid % SPIRAL_S];
    }
    __syncthreads();

    auto fill_async = [&](int s, int b) {
#pragma unroll
        for (int i = tid; i < 2048; i += 128) {
            int v = i >> 10;
            int rem = i & 1023;
            int tl = rem >> 4;
            int u = rem & 15;
            const void* g = &x[((size_t)tl * nverts + vidx[v * SPIRAL_S + s]) * 32 + u * 2];
            uint32_t d = (uint32_t)__cvta_generic_to_shared(&xg[b][v * 64 * 34 + tl * 34 + u * 2]);
            asm volatile("cp.async.ca.shared.global [%0], [%1], 4;" :: "r"(d), "l"(g));
        }
    };

    fill_async(0, 0);
    asm volatile("cp.async.commit_group;" ::: "memory");

    int v = tid >> 6;
    int t = tid & 63;
    float a0 = 0.f, a1 = 0.f, a2 = 0.f;
    for (int s = 0; s < SPIRAL_S; s++) {
        __syncthreads();   // compute(s-1) done before fill(s+1) overwrites its buffer
        if (s + 1 < SPIRAL_S) {
            fill_async(s + 1, (s + 1) & 1);
            asm volatile("cp.async.commit_group;" ::: "memory");
            asm volatile("cp.async.wait_group 1;" ::: "memory");
        } else {
            asm volatile("cp.async.wait_group 0;" ::: "memory");
        }
        __syncthreads();   // buffer s visible
        const uint32_t* xgu = (const uint32_t*)&xg[s & 1][v * 64 * 34];
        int rb = t * 17;
#pragma unroll
        for (int u = 0; u < 16; u++) {
            float2 f = __half22float2(*(const __half2*)&xgu[rb + u]);
            int kb = (s * 32 + u * 2) * 3;
            a0 += f.x * wfs[kb + 0] + f.y * wfs[kb + 3];
            a1 += f.x * wfs[kb + 1] + f.y * wfs[kb + 4];
            a2 += f.x * wfs[kb + 2] + f.y * wfs[kb + 5];
        }
    }
    int n = n0 + v;
    if (n < nverts) {
        size_t ob = ((size_t)t * nverts + n) * 3;
        out[ob + 0] = a0 + bf[0] + actor[(size_t)n * 3 + 0];
        out[ob + 1] = a1 + bf[1] + actor[(size_t)n * 3 + 1];
        out[ob + 2] = a2 + bf[2] + actor[(size_t)n * 3 + 2];
    }
}

// -------------------- host --------------------
extern "C" void kernel_launch(void* const* d_in, const int* in_sizes, int n_in_cnt,
                              void* d_out, int out_size) {
    const float* latent = (const float*)d_in[0];
    const float* actor  = (const float*)d_in[1];
    const int* sp0 = (const int*)d_in[2];
    const int* sp1 = (const int*)d_in[3];
    const int* sp2 = (const int*)d_in[4];
    const int* sp3 = (const int*)d_in[5];
    const int*   upr[4] = {(const int*)d_in[6], (const int*)d_in[9], (const int*)d_in[12], (const int*)d_in[15]};
    const int*   upc[4] = {(const int*)d_in[7], (const int*)d_in[10], (const int*)d_in[13], (const int*)d_in[16]};
    const float* upv[4] = {(const float*)d_in[8], (const float*)d_in[11], (const float*)d_in[14], (const float*)d_in[17]};
    const float* W0 = (const float*)d_in[18];
    const float* b0 = (const float*)d_in[19];
    const float* W1 = (const float*)d_in[20];
    const float* b1 = (const float*)d_in[21];
    const float* W2 = (const float*)d_in[22];
    const float* b2 = (const float*)d_in[23];
    const float* W3 = (const float*)d_in[24];
    const float* b3 = (const float*)d_in[25];
    const float* W4 = (const float*)d_in[26];
    const float* b4 = (const float*)d_in[27];
    const float* Wf = (const float*)d_in[28];
    const float* bf = (const float*)d_in[29];
    float* out = (float*)d_out;

    __half *A, *B;
    float *WT, *cval;
    int *ptr, *eid, *ccol;
    cudaGetSymbolAddress((void**)&A, g_bufA);
    cudaGetSymbolAddress((void**)&B, g_bufB);
    cudaGetSymbolAddress((void**)&WT, g_WT);
    cudaGetSymbolAddress((void**)&ptr, g_ptr);
    cudaGetSymbolAddress((void**)&eid, g_eid);
    cudaGetSymbolAddress((void**)&ccol, g_ccol);
    cudaGetSymbolAddress((void**)&cval, g_cval);

    const int LEV[5] = {5023, 1256, 314, 79, 20};
    int nnz[4] = {in_sizes[6], in_sizes[9], in_sizes[12], in_sizes[15]};

    // ---- descriptors ----
    TDesc td;
    td.W[0] = W1; td.K[0] = 1152; td.C[0] = 128;
    td.W[1] = W2; td.K[1] = 1152; td.C[1] = 64;
    td.W[2] = W3; td.K[2] = 576;  td.C[2] = 64;
    td.W[3] = W4; td.K[3] = 576;  td.C[3] = 32;
    td.W[4] = Wf; td.K[4] = 288;  td.C[4] = 3;
    int offH = 0, tot = 0;
    for (int l = 0; l < 5; l++) {
        td.offH[l] = offH;
        if (l < 4) offH += td.K[l] * td.C[l];
        tot += td.K[l] * td.C[l];
    }
    td.tot = tot;

    CsrDesc cd;
    int nzo = 0, ro = 0;
    for (int l = 0; l < 4; l++) {
        cd.rows[l] = upr[l]; cd.cols[l] = upc[l]; cd.vals[l] = upv[l];
        cd.nnz[l] = nnz[l];
        cd.nnzOff[l] = nzo; nzo += nnz[l];
        cd.nout[l] = LEV[l];
        cd.ptrOff[l] = ro + l;
        ro += LEV[l];
    }
    cd.nnzOff[4] = nzo;

    // ---- fused prologue: CSR + dense + weight pack in one launch ----
    fused_prologue<<<PRO_TOTAL_BLKS, 1024>>>(cd, ptr, eid, ccol, cval,
                                             latent, W0, b0, A, td, WT);

    const uint2* BW0 = (const uint2*)((const __half*)WT + td.offH[0]);
    const uint2* BW1 = (const uint2*)((const __half*)WT + td.offH[1]);
    const uint2* BW2 = (const uint2*)((const __half*)WT + td.offH[2]);
    const uint2* BW3 = (const uint2*)((const __half*)WT + td.offH[3]);
    const float* WFf = WT + WT_FINAL_F32_OFF;

    // ---- level 3: pool 20->79 (C=128, TCH=8), conv 128->128 (co split x4) ----
    pool_gather<128, 8><<<dim3(79, 8), 128>>>(A, B, ptr + cd.ptrOff[3], ccol, cval, 20, 79);
    conv_fp16<128, 128, 32><<<dim3(40, 1, 4), 128>>>(B, sp3, BW0, b1, A, 79);

    // ---- level 2: pool 79->314 (C=128, TCH=8), conv 128->64 (co split x2) ----
    pool_gather<128, 8><<<dim3(314, 8), 128>>>(A, B, ptr + cd.ptrOff[2], ccol, cval, 79, 314);
    conv_fp16<128, 64, 32><<<dim3(157, 1, 2), 128>>>(B, sp2, BW1, b2, A, 314);

    // ---- level 1: pool 314->1256 (C=64, TCH=16), conv 64->64 ----
    pool_gather<64, 16><<<dim3(1256, 4), 128>>>(A, B, ptr + cd.ptrOff[1], ccol, cval, 314, 1256);
    conv_fp16<64, 64, 64><<<dim3(628, 1, 1), 128>>>(B, sp1, BW2, b3, A, 1256);

    // ---- level 0: pool 1256->5023 (C=64, TCH=16), conv 64->32 ----
    pool_gather<64, 16><<<dim3(5023, 4), 128>>>(A, B, ptr + cd.ptrOff[0], ccol, cval, 1256, 5023);
    conv_fp16<64, 32, 32><<<dim3(2512, 1, 1), 128>>>(B, sp0, BW3, b4, A, 5023);

    // ---- final conv 32->3 + actor -> d_out (2 vertices/block) ----
    final_kernel<<<2512, 128>>>(A, sp0, WFf, bf, actor, out, 5023);

    (void)in_sizes; (void)n_in_cnt; (void)out_size;
}

// round 16
// speedup vs baseline: 1.0419x; 1.0419x over previous
#include <cuda_runtime.h>
#include <cuda_fp16.h>
#include <math.h>
#include <stdint.h>

#define T_FRAMES 64
#define SPIRAL_S 9

// -------------------- static device scratch (no allocations) --------------------
__device__ __half g_bufA[10287104];  // conv/dense outputs (fp16)
__device__ __half g_bufB[20574208];  // pooled tensors (fp16)
__device__ float  g_WT[277344];      // packed weights: fp16 frag images (l<4), final fp32
__device__ int    g_ptr[6680];       // CSR row pointers
__device__ int    g_eid[20016];      // CSR entry ids
__device__ int    g_ccol[20016];     // CSR cols
__device__ float  g_cval[20016];     // CSR vals

#define WT_FINAL_F32_OFF 138240

struct CsrDesc {
    const int*   rows[4];
    const int*   cols[4];
    const float* vals[4];
    int nnz[4];
    int nnzOff[5];
    int nout[4];
    int ptrOff[4];
};

struct TDesc {
    const float* W[5];
    int K[5];
    int C[5];
    int offH[5];
    int tot;
};

// -------------------- fused prologue: CSR (blocks 0-3) + dense (4-163) + pack (164+) ------
#define PRO_DENSE_BLKS 160
#define PRO_PACK_BLKS  40
#define PRO_TOTAL_BLKS (4 + PRO_DENSE_BLKS + PRO_PACK_BLKS)

__global__ void __launch_bounds__(1024)
fused_prologue(CsrDesc cd, int* __restrict__ ptr, int* __restrict__ eid,
               int* __restrict__ ccol, float* __restrict__ cval,
               const float* __restrict__ latent, const float* __restrict__ W0,
               const float* __restrict__ b0, __half* __restrict__ dout,
               TDesc td, float* __restrict__ WT) {
    __shared__ int cnt[5024];
    __shared__ int sptr[5024];
    __shared__ int ssum[1024];

    int bid = blockIdx.x;
    int tid = threadIdx.x;

    if (bid < 4) {
        // ---- CSR build (one level per block) ----
        int l = bid;
        int n = cd.nout[l];
        int nnz = cd.nnz[l];
        int nb = cd.nnzOff[l];
        int pbase = cd.ptrOff[l];
        const int* rows = cd.rows[l];

        for (int i = tid; i <= n; i += 1024) cnt[i] = 0;
        __syncthreads();
        for (int e = tid; e < nnz; e += 1024) atomicAdd(&cnt[rows[e]], 1);
        __syncthreads();

        int v[5], loc[5];
        int s = 0;
#pragma unroll
        for (int j = 0; j < 5; j++) {
            int idx = tid * 5 + j;
            loc[j] = s;
            v[j] = (idx < n) ? cnt[idx] : 0;
            s += v[j];
        }
        ssum[tid] = s;
        __syncthreads();
        for (int off = 1; off < 1024; off <<= 1) {
            int t = (tid >= off) ? ssum[tid - off] : 0;
            __syncthreads();
            ssum[tid] += t;
            __syncthreads();
        }
        int ex = (tid > 0) ? ssum[tid - 1] : 0;
#pragma unroll
        for (int j = 0; j < 5; j++) {
            int idx = tid * 5 + j;
            if (idx < n) sptr[idx] = nb + ex + loc[j];
        }
        if (tid == 0) sptr[n] = nb + nnz;
        __syncthreads();

        for (int i = tid; i <= n; i += 1024) cnt[i] = 0;
        __syncthreads();
        for (int e = tid; e < nnz; e += 1024) {
            int r = rows[e];
            int pos = sptr[r] + atomicAdd(&cnt[r], 1);
            eid[pos] = e;
        }
        __syncthreads();

        const int* cols = cd.cols[l];
        const float* vals = cd.vals[l];
        for (int r = tid; r < n; r += 1024) {
            int j0 = sptr[r], j1 = sptr[r + 1];
            for (int a = j0 + 1; a < j1; a++) {
                int key = eid[a];
                int b = a - 1;
                while (b >= j0 && eid[b] > key) { eid[b + 1] = eid[b]; b--; }
                eid[b + 1] = key;
            }
            for (int j = j0; j < j1; j++) {
                int e = eid[j];
                ccol[j] = cols[e];
                cval[j] = vals[e];
            }
        }
        for (int i = tid; i <= n; i += 1024) ptr[pbase + i] = sptr[i];
    } else if (bid < 4 + PRO_DENSE_BLKS) {
        // ---- dense: warp-per-output loop over 64*2560 outputs ----
        int warp = tid >> 5;
        int lane = tid & 31;
        int gw = (bid - 4) * 32 + warp;
        for (int o = gw; o < 64 * 2560; o += PRO_DENSE_BLKS * 32) {
            int t = o / 2560;
            int j = o - t * 2560;
            const float* lrow = latent + t * 128;
            const float* wrow = W0 + (size_t)j * 128;
            float acc = 0.f;
#pragma unroll
            for (int k = lane; k < 128; k += 32) acc += lrow[k] * wrow[k];
#pragma unroll
            for (int off = 16; off > 0; off >>= 1) acc += __shfl_down_sync(0xffffffffu, acc, off);
            if (lane == 0) dout[(size_t)t * 2560 + j] = __float2half(acc + b0[j]);
        }
    } else {
        // ---- weight pack, grid-stride ----
        __half* WH = (__half*)WT;
        int i = (bid - 4 - PRO_DENSE_BLKS) * 1024 + tid;
        int st = PRO_PACK_BLKS * 1024;
        for (; i < td.tot; i += st) {
            int l = 0, o = i;
            while (l < 4 && o >= td.K[l] * td.C[l]) { o -= td.K[l] * td.C[l]; l++; }
            int K = td.K[l], C = td.C[l];
            int k = o / C;
            int c = o - k * C;
            float v = td.W[l][(size_t)c * K + k];
            if (l < 4) {
                int kc = k >> 4;
                int kk = k & 15;
                int nt = c >> 3;
                int lane2 = (c & 7) * 4 + ((kk >> 1) & 3);
                int reg = kk >> 3;
                int h = kk & 1;
                int idx32 = (kc * (C >> 3) + nt) * 64 + lane2 * 2 + reg;
                WH[td.offH[l] + idx32 * 2 + h] = __float2half(v);
            } else {
                WT[WT_FINAL_F32_OFF + o] = v;
            }
        }
    }
}

// -------------------- gather pool: fp16->fp16, grid (n_out, 64/TCH), 128 threads ----------
template <int C, int TCH>
__global__ void __launch_bounds__(128)
pool_gather(const __half* __restrict__ x, __half* __restrict__ out,
            const int* __restrict__ ptr, const int* __restrict__ ccol,
            const float* __restrict__ cval, int n_in, int n_out) {
    constexpr int CH = C / 2;
    constexpr int TGI = 128 / CH;        // t-groups per block
    constexpr int TPG = TCH / TGI;       // frames per t-group (multiple of 4)
    static_assert(TPG >= 4 && TPG % 4 == 0, "TPG must be multiple of 4");
    int r = blockIdx.x;
    int tb = blockIdx.y * TCH;
    int tid = threadIdx.x;
    int c2 = tid % CH;
    int tg = tid / CH;
    int j0 = ptr[r], j1 = ptr[r + 1];
    int deg = j1 - j0;
    __shared__ int scol[32];
    __shared__ float sval[32];
    int dm = deg < 32 ? deg : 32;
    if (tid < dm) { scol[tid] = ccol[j0 + tid]; sval[tid] = cval[j0 + tid]; }
    __syncthreads();
    size_t sx = (size_t)n_in * CH;
    size_t so = (size_t)n_out * CH;
    const __half2* x2 = (const __half2*)x;
    __half2* o2 = (__half2*)out;
    int t0 = tb + tg * TPG;
    for (int t = t0; t < t0 + TPG; t += 4) {
        float2 a0 = make_float2(0.f, 0.f), a1 = a0, a2 = a0, a3 = a0;
        for (int j = 0; j < dm; j++) {
            float v = sval[j];
            size_t base = ((size_t)t * n_in + scol[j]) * CH + c2;
            float2 f0 = __half22float2(x2[base]);
            float2 f1 = __half22float2(x2[base + sx]);
            float2 f2 = __half22float2(x2[base + 2 * sx]);
            float2 f3 = __half22float2(x2[base + 3 * sx]);
            a0.x += v * f0.x; a0.y += v * f0.y;
            a1.x += v * f1.x; a1.y += v * f1.y;
            a2.x += v * f2.x; a2.y += v * f2.y;
            a3.x += v * f3.x; a3.y += v * f3.y;
        }
        for (int j = 32; j < deg; j++) {
            float v = cval[j0 + j];
            size_t base = ((size_t)t * n_in + ccol[j0 + j]) * CH + c2;
            float2 f0 = __half22float2(x2[base]);
            float2 f1 = __half22float2(x2[base + sx]);
            float2 f2 = __half22float2(x2[base + 2 * sx]);
            float2 f3 = __half22float2(x2[base + 3 * sx]);
            a0.x += v * f0.x; a0.y += v * f0.y;
            a1.x += v * f1.x; a1.y += v * f1.y;
            a2.x += v * f2.x; a2.y += v * f2.y;
            a3.x += v * f3.x; a3.y += v * f3.y;
        }
        size_t ob = ((size_t)t * n_out + r) * CH + c2;
        o2[ob] = __floats2half2_rn(a0.x, a0.y);
        o2[ob + so] = __floats2half2_rn(a1.x, a1.y);
        o2[ob + 2 * so] = __floats2half2_rn(a2.x, a2.y);
        o2[ob + 3 * so] = __floats2half2_rn(a3.x, a3.y);
    }
}

// -------------------- spiral conv: fp16 mma + ldmatrix + 2-stage cp.async ----------
template <int CIN, int COUT, int CON>
__global__ void __launch_bounds__(128)
conv_fp16(const __half* __restrict__ x, const int* __restrict__ spiral,
          const uint2* __restrict__ Bpk, const float* __restrict__ bias,
          __half* __restrict__ out, int nverts) {
    constexpr int K   = SPIRAL_S * CIN;
    constexpr int NCH = K / 32;
    constexpr int NT  = CON / 8;
    constexpr int NTILES = COUT / 8;

    __shared__ __align__(16) __half xg[2][128 * 40];
    __shared__ int vidx[2 * SPIRAL_S];

    int tid = threadIdx.x;
    int warp = tid >> 5;
    int lane = tid & 31;
    int n0 = blockIdx.x * 2;
    int co0 = blockIdx.z * CON;
    int nt0 = co0 >> 3;

    if (tid < 2 * SPIRAL_S) {
        int v = n0 + tid / SPIRAL_S;
        if (v >= nverts) v = nverts - 1;
        vidx[tid] = spiral[v * SPIRAL_S + tid % SPIRAL_S];
    }
    __syncthreads();

    float acc[2][NT][4];
#pragma unroll
    for (int mt = 0; mt < 2; mt++)
#pragma unroll
        for (int nt = 0; nt < NT; nt++)
#pragma unroll
            for (int j = 0; j < 4; j++) acc[mt][nt][j] = 0.f;

    auto fill_async = [&](int c, int b) {
        int s = (c * 32) / CIN;
        int ci0 = (c * 32) % CIN;
#pragma unroll
        for (int i = tid; i < 1024; i += 128) {
            int row = i >> 3;
            int c8 = i & 7;
            int v = row >> 6;
            int t = row & 63;
            const void* g = &x[((size_t)t * nverts + vidx[v * SPIRAL_S + s]) * CIN + ci0 + c8 * 4];
            uint32_t d = (uint32_t)__cvta_generic_to_shared(&xg[b][row * 40 + c8 * 4]);
            asm volatile("cp.async.ca.shared.global [%0], [%1], 8;" :: "r"(d), "l"(g));
        }
    };

    fill_async(0, 0);
    asm volatile("cp.async.commit_group;" ::: "memory");

    int rbase = warp * 32;
    int lm_row = (lane & 7) + ((lane >> 3) & 1) * 8;
    int lm_col = (lane >> 4) * 8;

    for (int c = 0; c < NCH; c++) {
        __syncthreads();
        if (c + 1 < NCH) {
            fill_async(c + 1, (c + 1) & 1);
            asm volatile("cp.async.commit_group;" ::: "memory");
            asm volatile("cp.async.wait_group 1;" ::: "memory");
        } else {
            asm volatile("cp.async.wait_group 0;" ::: "memory");
        }
        __syncthreads();
        const __half* xb = xg[c & 1];
#pragma unroll
        for (int j = 0; j < 2; j++) {
            uint32_t a[2][4];
#pragma unroll
            for (int mt = 0; mt < 2; mt++) {
                uint32_t ad = (uint32_t)__cvta_generic_to_shared(
                    &xb[(rbase + mt * 16 + lm_row) * 40 + j * 16 + lm_col]);
                asm volatile(
                    "ldmatrix.sync.aligned.m8n8.x4.shared.b16 {%0,%1,%2,%3}, [%4];"
                    : "=r"(a[mt][0]), "=r"(a[mt][1]), "=r"(a[mt][2]), "=r"(a[mt][3])
                    : "r"(ad));
            }
            int kc = c * 2 + j;
            const uint2* bp = Bpk + (size_t)(kc * NTILES + nt0) * 32 + lane;
#pragma unroll
            for (int nt = 0; nt < NT; nt++) {
                uint2 bb = bp[nt * 32];
#pragma unroll
                for (int mt = 0; mt < 2; mt++) {
                    asm volatile(
                        "mma.sync.aligned.m16n8k16.row.col.f32.f16.f16.f32 "
                        "{%0,%1,%2,%3}, {%4,%5,%6,%7}, {%8,%9}, {%0,%1,%2,%3};"
                        : "+f"(acc[mt][nt][0]), "+f"(acc[mt][nt][1]),
                          "+f"(acc[mt][nt][2]), "+f"(acc[mt][nt][3])
                        : "r"(a[mt][0]), "r"(a[mt][1]), "r"(a[mt][2]), "r"(a[mt][3]),
                          "r"(bb.x), "r"(bb.y));
                }
            }
        }
    }

#pragma unroll
    for (int mt = 0; mt < 2; mt++) {
        int row0 = rbase + mt * 16 + (lane >> 2);
#pragma unroll
        for (int hf = 0; hf < 2; hf++) {
            int row = row0 + hf * 8;
            int v = row >> 6;
            int t = row & 63;
            int n = n0 + v;
            if (n >= nverts) continue;
#pragma unroll
            for (int nt = 0; nt < NT; nt++) {
                int co = co0 + nt * 8 + (lane & 3) * 2;
                float2 bv = *(const float2*)&bias[co];
                float v0 = acc[mt][nt][hf * 2 + 0] + bv.x;
                float v1 = acc[mt][nt][hf * 2 + 1] + bv.y;
                v0 = (v0 > 0.f) ? v0 : (__expf(v0) - 1.f);
                v1 = (v1 > 0.f) ? v1 : (__expf(v1) - 1.f);
                *(__half2*)&out[((size_t)t * nverts + n) * COUT + co] = __floats2half2_rn(v0, v1);
            }
        }
    }
}

// -------------------- final conv 32->3 + actor: cp.async double-buffered --------------------
__global__ void __launch_bounds__(64)
final_kernel(const __half* __restrict__ x, const int* __restrict__ spiral,
             const float* __restrict__ WTf,  // [288][3]
             const float* __restrict__ bf,
             const float* __restrict__ actor,
             float* __restrict__ out, int nverts) {
    __shared__ float wfs[864];
    __shared__ __align__(8) __half xg[2][64 * 34];
    __shared__ int vidx[SPIRAL_S];
    int n = blockIdx.x;
    int tid = threadIdx.x;
    for (int i = tid; i < 864; i += 64) wfs[i] = WTf[i];
    if (tid < SPIRAL_S) vidx[tid] = spiral[n * SPIRAL_S + tid];
    __syncthreads();

    auto fill_async = [&](int s, int b) {
        int v = vidx[s];
#pragma unroll
        for (int i = tid; i < 1024; i += 64) {
            int tl = i >> 4;
            int u = i & 15;
            const void* g = &x[((size_t)tl * nverts + v) * 32 + u * 2];
            uint32_t d = (uint32_t)__cvta_generic_to_shared(&xg[b][tl * 34 + u * 2]);
            asm volatile("cp.async.ca.shared.global [%0], [%1], 4;" :: "r"(d), "l"(g));
        }
    };

    fill_async(0, 0);
    asm volatile("cp.async.commit_group;" ::: "memory");

    float a0 = 0.f, a1 = 0.f, a2 = 0.f;
    for (int s = 0; s < SPIRAL_S; s++) {
        __syncthreads();
        if (s + 1 < SPIRAL_S) {
            fill_async(s + 1, (s + 1) & 1);
            asm volatile("cp.async.commit_group;" ::: "memory");
            asm volatile("cp.async.wait_group 1;" ::: "memory");
        } else {
            asm volatile("cp.async.wait_group 0;" ::: "memory");
        }
        __syncthreads();
        const uint32_t* xgu = (const uint32_t*)xg[s & 1];
        int rb = tid * 17;
#pragma unroll
        for (int u = 0; u < 16; u++) {
            float2 f = __half22float2(*(const __half2*)&xgu[rb + u]);
            int kb = (s * 32 + u * 2) * 3;
            a0 += f.x * wfs[kb + 0] + f.y * wfs[kb + 3];
            a1 += f.x * wfs[kb + 1] + f.y * wfs[kb + 4];
            a2 += f.x * wfs[kb + 2] + f.y * wfs[kb + 5];
        }
    }
    size_t ob = ((size_t)tid * nverts + n) * 3;
    out[ob + 0] = a0 + bf[0] + actor[(size_t)n * 3 + 0];
    out[ob + 1] = a1 + bf[1] + actor[(size_t)n * 3 + 1];
    out[ob + 2] = a2 + bf[2] + actor[(size_t)n * 3 + 2];
}

// -------------------- host --------------------
extern "C" void kernel_launch(void* const* d_in, const int* in_sizes, int n_in_cnt,
                              void* d_out, int out_size) {
    const float* latent = (const float*)d_in[0];
    const float* actor  = (const float*)d_in[1];
    const int* sp0 = (const int*)d_in[2];
    const int* sp1 = (const int*)d_in[3];
    const int* sp2 = (const int*)d_in[4];
    const int* sp3 = (const int*)d_in[5];
    const int*   upr[4] = {(const int*)d_in[6], (const int*)d_in[9], (const int*)d_in[12], (const int*)d_in[15]};
    const int*   upc[4] = {(const int*)d_in[7], (const int*)d_in[10], (const int*)d_in[13], (const int*)d_in[16]};
    const float* upv[4] = {(const float*)d_in[8], (const float*)d_in[11], (const float*)d_in[14], (const float*)d_in[17]};
    const float* W0 = (const float*)d_in[18];
    const float* b0 = (const float*)d_in[19];
    const float* W1 = (const float*)d_in[20];
    const float* b1 = (const float*)d_in[21];
    const float* W2 = (const float*)d_in[22];
    const float* b2 = (const float*)d_in[23];
    const float* W3 = (const float*)d_in[24];
    const float* b3 = (const float*)d_in[25];
    const float* W4 = (const float*)d_in[26];
    const float* b4 = (const float*)d_in[27];
    const float* Wf = (const float*)d_in[28];
    const float* bf = (const float*)d_in[29];
    float* out = (float*)d_out;

    __half *A, *B;
    float *WT, *cval;
    int *ptr, *eid, *ccol;
    cudaGetSymbolAddress((void**)&A, g_bufA);
    cudaGetSymbolAddress((void**)&B, g_bufB);
    cudaGetSymbolAddress((void**)&WT, g_WT);
    cudaGetSymbolAddress((void**)&ptr, g_ptr);
    cudaGetSymbolAddress((void**)&eid, g_eid);
    cudaGetSymbolAddress((void**)&ccol, g_ccol);
    cudaGetSymbolAddress((void**)&cval, g_cval);

    const int LEV[5] = {5023, 1256, 314, 79, 20};
    int nnz[4] = {in_sizes[6], in_sizes[9], in_sizes[12], in_sizes[15]};

    // ---- descriptors ----
    TDesc td;
    td.W[0] = W1; td.K[0] = 1152; td.C[0] = 128;
    td.W[1] = W2; td.K[1] = 1152; td.C[1] = 64;
    td.W[2] = W3; td.K[2] = 576;  td.C[2] = 64;
    td.W[3] = W4; td.K[3] = 576;  td.C[3] = 32;
    td.W[4] = Wf; td.K[4] = 288;  td.C[4] = 3;
    int offH = 0, tot = 0;
    for (int l = 0; l < 5; l++) {
        td.offH[l] = offH;
        if (l < 4) offH += td.K[l] * td.C[l];
        tot += td.K[l] * td.C[l];
    }
    td.tot = tot;

    CsrDesc cd;
    int nzo = 0, ro = 0;
    for (int l = 0; l < 4; l++) {
        cd.rows[l] = upr[l]; cd.cols[l] = upc[l]; cd.vals[l] = upv[l];
        cd.nnz[l] = nnz[l];
        cd.nnzOff[l] = nzo; nzo += nnz[l];
        cd.nout[l] = LEV[l];
        cd.ptrOff[l] = ro + l;
        ro += LEV[l];
    }
    cd.nnzOff[4] = nzo;

    // ---- fused prologue: CSR + dense + weight pack in one launch ----
    fused_prologue<<<PRO_TOTAL_BLKS, 1024>>>(cd, ptr, eid, ccol, cval,
                                             latent, W0, b0, A, td, WT);

    const uint2* BW0 = (const uint2*)((const __half*)WT + td.offH[0]);
    const uint2* BW1 = (const uint2*)((const __half*)WT + td.offH[1]);
    const uint2* BW2 = (const uint2*)((const __half*)WT + td.offH[2]);
    const uint2* BW3 = (const uint2*)((const __half*)WT + td.offH[3]);
    const float* WFf = WT + WT_FINAL_F32_OFF;

    // ---- level 3: pool 20->79 (C=128, TCH=8), conv 128->128 (co split x4) ----
    pool_gather<128, 8><<<dim3(79, 8), 128>>>(A, B, ptr + cd.ptrOff[3], ccol, cval, 20, 79);
    conv_fp16<128, 128, 32><<<dim3(40, 1, 4), 128>>>(B, sp3, BW0, b1, A, 79);

    // ---- level 2: pool 79->314 (C=128, TCH=8), conv 128->64 (co split x2) ----
    pool_gather<128, 8><<<dim3(314, 8), 128>>>(A, B, ptr + cd.ptrOff[2], ccol, cval, 79, 314);
    conv_fp16<128, 64, 32><<<dim3(157, 1, 2), 128>>>(B, sp2, BW1, b2, A, 314);

    // ---- level 1: pool 314->1256 (C=64, TCH=16), conv 64->64 ----
    pool_gather<64, 16><<<dim3(1256, 4), 128>>>(A, B, ptr + cd.ptrOff[1], ccol, cval, 314, 1256);
    conv_fp16<64, 64, 64><<<dim3(628, 1, 1), 128>>>(B, sp1, BW2, b3, A, 1256);

    // ---- level 0: pool 1256->5023 (C=64, TCH=16), conv 64->32 ----
    pool_gather<64, 16><<<dim3(5023, 4), 128>>>(A, B, ptr + cd.ptrOff[0], ccol, cval, 1256, 5023);
    conv_fp16<64, 32, 32><<<dim3(2512, 1, 1), 128>>>(B, sp0, BW3, b4, A, 5023);

    // ---- final conv 32->3 + actor -> d_out ----
    final_kernel<<<5023, 64>>>(A, sp0, WFf, bf, actor, out, 5023);

    (void)in_sizes; (void)n_in_cnt; (void)out_size;
}

// round 17
// speedup vs baseline: 1.1739x; 1.1267x over previous
#include <cuda_runtime.h>
#include <cuda_fp16.h>
#include <math.h>
#include <stdint.h>

#define T_FRAMES 64
#define SPIRAL_S 9

// -------------------- static device scratch (no allocations) --------------------
__device__ __half g_bufA[10287104];  // conv/dense outputs (fp16)
__device__ __half g_bufB[20574208];  // pooled tensors (fp16)
__device__ float  g_WT[277344];      // packed weights: fp16 frag images (l<4), final fp32
__device__ int    g_ptr[6680];       // CSR row pointers
__device__ int    g_eid[20016];      // CSR entry ids
__device__ int    g_ccol[20016];     // CSR cols
__device__ float  g_cval[20016];     // CSR vals

#define WT_FINAL_F32_OFF 138240

struct CsrDesc {
    const int*   rows[4];
    const int*   cols[4];
    const float* vals[4];
    int nnz[4];
    int nnzOff[5];
    int nout[4];
    int ptrOff[4];
};

struct TDesc {
    const float* W[5];
    int K[5];
    int C[5];
    int offH[5];
    int tot;
};

// -------------------- fused prologue: CSR (blocks 0-3) + dense (4-163) + pack (164+) ------
#define PRO_DENSE_BLKS 160
#define PRO_PACK_BLKS  40
#define PRO_TOTAL_BLKS (4 + PRO_DENSE_BLKS + PRO_PACK_BLKS)

__global__ void __launch_bounds__(1024)
fused_prologue(CsrDesc cd, int* __restrict__ ptr, int* __restrict__ eid,
               int* __restrict__ ccol, float* __restrict__ cval,
               const float* __restrict__ latent, const float* __restrict__ W0,
               const float* __restrict__ b0, __half* __restrict__ dout,
               TDesc td, float* __restrict__ WT) {
    __shared__ int cnt[5024];
    __shared__ int sptr[5024];
    __shared__ int ssum[1024];

    int bid = blockIdx.x;
    int tid = threadIdx.x;

    if (bid < 4) {
        // ---- CSR build (one level per block) ----
        int l = bid;
        int n = cd.nout[l];
        int nnz = cd.nnz[l];
        int nb = cd.nnzOff[l];
        int pbase = cd.ptrOff[l];
        const int* rows = cd.rows[l];

        for (int i = tid; i <= n; i += 1024) cnt[i] = 0;
        __syncthreads();
        for (int e = tid; e < nnz; e += 1024) atomicAdd(&cnt[rows[e]], 1);
        __syncthreads();

        int v[5], loc[5];
        int s = 0;
#pragma unroll
        for (int j = 0; j < 5; j++) {
            int idx = tid * 5 + j;
            loc[j] = s;
            v[j] = (idx < n) ? cnt[idx] : 0;
            s += v[j];
        }
        ssum[tid] = s;
        __syncthreads();
        for (int off = 1; off < 1024; off <<= 1) {
            int t = (tid >= off) ? ssum[tid - off] : 0;
            __syncthreads();
            ssum[tid] += t;
            __syncthreads();
        }
        int ex = (tid > 0) ? ssum[tid - 1] : 0;
#pragma unroll
        for (int j = 0; j < 5; j++) {
            int idx = tid * 5 + j;
            if (idx < n) sptr[idx] = nb + ex + loc[j];
        }
        if (tid == 0) sptr[n] = nb + nnz;
        __syncthreads();

        for (int i = tid; i <= n; i += 1024) cnt[i] = 0;
        __syncthreads();
        for (int e = tid; e < nnz; e += 1024) {
            int r = rows[e];
            int pos = sptr[r] + atomicAdd(&cnt[r], 1);
            eid[pos] = e;
        }
        __syncthreads();

        const int* cols = cd.cols[l];
        const float* vals = cd.vals[l];
        for (int r = tid; r < n; r += 1024) {
            int j0 = sptr[r], j1 = sptr[r + 1];
            for (int a = j0 + 1; a < j1; a++) {
                int key = eid[a];
                int b = a - 1;
                while (b >= j0 && eid[b] > key) { eid[b + 1] = eid[b]; b--; }
                eid[b + 1] = key;
            }
            for (int j = j0; j < j1; j++) {
                int e = eid[j];
                ccol[j] = cols[e];
                cval[j] = vals[e];
            }
        }
        for (int i = tid; i <= n; i += 1024) ptr[pbase + i] = sptr[i];
    } else if (bid < 4 + PRO_DENSE_BLKS) {
        // ---- dense: warp-per-output loop over 64*2560 outputs ----
        int warp = tid >> 5;
        int lane = tid & 31;
        int gw = (bid - 4) * 32 + warp;
        for (int o = gw; o < 64 * 2560; o += PRO_DENSE_BLKS * 32) {
            int t = o / 2560;
            int j = o - t * 2560;
            const float* lrow = latent + t * 128;
            const float* wrow = W0 + (size_t)j * 128;
            float acc = 0.f;
#pragma unroll
            for (int k = lane; k < 128; k += 32) acc += lrow[k] * wrow[k];
#pragma unroll
            for (int off = 16; off > 0; off >>= 1) acc += __shfl_down_sync(0xffffffffu, acc, off);
            if (lane == 0) dout[(size_t)t * 2560 + j] = __float2half(acc + b0[j]);
        }
    } else {
        // ---- weight pack, grid-stride ----
        __half* WH = (__half*)WT;
        int i = (bid - 4 - PRO_DENSE_BLKS) * 1024 + tid;
        int st = PRO_PACK_BLKS * 1024;
        for (; i < td.tot; i += st) {
            int l = 0, o = i;
            while (l < 4 && o >= td.K[l] * td.C[l]) { o -= td.K[l] * td.C[l]; l++; }
            int K = td.K[l], C = td.C[l];
            int k = o / C;
            int c = o - k * C;
            float v = td.W[l][(size_t)c * K + k];
            if (l < 4) {
                int kc = k >> 4;
                int kk = k & 15;
                int nt = c >> 3;
                int lane2 = (c & 7) * 4 + ((kk >> 1) & 3);
                int reg = kk >> 3;
                int h = kk & 1;
                int idx32 = (kc * (C >> 3) + nt) * 64 + lane2 * 2 + reg;
                WH[td.offH[l] + idx32 * 2 + h] = __float2half(v);
            } else {
                WT[WT_FINAL_F32_OFF + o] = v;
            }
        }
    }
}

// -------------------- gather pool: fp16->fp16, grid (n_out, 64/TCH), 128 threads ----------
template <int C, int TCH>
__global__ void __launch_bounds__(128)
pool_gather(const __half* __restrict__ x, __half* __restrict__ out,
            const int* __restrict__ ptr, const int* __restrict__ ccol,
            const float* __restrict__ cval, int n_in, int n_out) {
    constexpr int CH = C / 2;
    constexpr int TGI = 128 / CH;        // t-groups per block
    constexpr int TPG = TCH / TGI;       // frames per t-group (multiple of 4)
    static_assert(TPG >= 4 && TPG % 4 == 0, "TPG must be multiple of 4");
    int r = blockIdx.x;
    int tb = blockIdx.y * TCH;
    int tid = threadIdx.x;
    int c2 = tid % CH;
    int tg = tid / CH;
    int j0 = ptr[r], j1 = ptr[r + 1];
    int deg = j1 - j0;
    __shared__ int scol[32];
    __shared__ float sval[32];
    int dm = deg < 32 ? deg : 32;
    if (tid < dm) { scol[tid] = ccol[j0 + tid]; sval[tid] = cval[j0 + tid]; }
    __syncthreads();
    size_t sx = (size_t)n_in * CH;
    size_t so = (size_t)n_out * CH;
    const __half2* x2 = (const __half2*)x;
    __half2* o2 = (__half2*)out;
    int t0 = tb + tg * TPG;
    for (int t = t0; t < t0 + TPG; t += 4) {
        float2 a0 = make_float2(0.f, 0.f), a1 = a0, a2 = a0, a3 = a0;
        for (int j = 0; j < dm; j++) {
            float v = sval[j];
            size_t base = ((size_t)t * n_in + scol[j]) * CH + c2;
            float2 f0 = __half22float2(x2[base]);
            float2 f1 = __half22float2(x2[base + sx]);
            float2 f2 = __half22float2(x2[base + 2 * sx]);
            float2 f3 = __half22float2(x2[base + 3 * sx]);
            a0.x += v * f0.x; a0.y += v * f0.y;
            a1.x += v * f1.x; a1.y += v * f1.y;
            a2.x += v * f2.x; a2.y += v * f2.y;
            a3.x += v * f3.x; a3.y += v * f3.y;
        }
        for (int j = 32; j < deg; j++) {
            float v = cval[j0 + j];
            size_t base = ((size_t)t * n_in + ccol[j0 + j]) * CH + c2;
            float2 f0 = __half22float2(x2[base]);
            float2 f1 = __half22float2(x2[base + sx]);
            float2 f2 = __half22float2(x2[base + 2 * sx]);
            float2 f3 = __half22float2(x2[base + 3 * sx]);
            a0.x += v * f0.x; a0.y += v * f0.y;
            a1.x += v * f1.x; a1.y += v * f1.y;
            a2.x += v * f2.x; a2.y += v * f2.y;
            a3.x += v * f3.x; a3.y += v * f3.y;
        }
        size_t ob = ((size_t)t * n_out + r) * CH + c2;
        o2[ob] = __floats2half2_rn(a0.x, a0.y);
        o2[ob + so] = __floats2half2_rn(a1.x, a1.y);
        o2[ob + 2 * so] = __floats2half2_rn(a2.x, a2.y);
        o2[ob + 3 * so] = __floats2half2_rn(a3.x, a3.y);
    }
}

// ------ spiral conv: fp16 mma + ldmatrix + 2-stage cp.async (16B fills) ------
template <int CIN, int COUT, int CON>
__global__ void __launch_bounds__(128)
conv_fp16(const __half* __restrict__ x, const int* __restrict__ spiral,
          const uint2* __restrict__ Bpk, const float* __restrict__ bias,
          __half* __restrict__ out, int nverts) {
    constexpr int K   = SPIRAL_S * CIN;
    constexpr int NCH = K / 32;
    constexpr int NT  = CON / 8;
    constexpr int NTILES = COUT / 8;

    __shared__ __align__(16) __half xg[2][128 * 40];
    __shared__ int vidx[2 * SPIRAL_S];

    int tid = threadIdx.x;
    int warp = tid >> 5;
    int lane = tid & 31;
    int n0 = blockIdx.x * 2;
    int co0 = blockIdx.z * CON;
    int nt0 = co0 >> 3;

    if (tid < 2 * SPIRAL_S) {
        int v = n0 + tid / SPIRAL_S;
        if (v >= nverts) v = nverts - 1;
        vidx[tid] = spiral[v * SPIRAL_S + tid % SPIRAL_S];
    }
    __syncthreads();

    float acc[2][NT][4];
#pragma unroll
    for (int mt = 0; mt < 2; mt++)
#pragma unroll
        for (int nt = 0; nt < NT; nt++)
#pragma unroll
            for (int j = 0; j < 4; j++) acc[mt][nt][j] = 0.f;

    // 16-byte cp.async fills: 512 ops per chunk (4 per thread).
    // row pitch 40 halves = 80 B (16B-aligned); global offsets 16B-aligned
    // since CIN*2 in {128,256} and ci0*2 multiple of 64.
    auto fill_async = [&](int c, int b) {
        int s = (c * 32) / CIN;
        int ci0 = (c * 32) % CIN;
#pragma unroll
        for (int i = tid; i < 512; i += 128) {
            int row = i >> 2;
            int c16 = i & 3;
            int v = row >> 6;
            int t = row & 63;
            const void* g = &x[((size_t)t * nverts + vidx[v * SPIRAL_S + s]) * CIN + ci0 + c16 * 8];
            uint32_t d = (uint32_t)__cvta_generic_to_shared(&xg[b][row * 40 + c16 * 8]);
            asm volatile("cp.async.cg.shared.global [%0], [%1], 16;" :: "r"(d), "l"(g));
        }
    };

    fill_async(0, 0);
    asm volatile("cp.async.commit_group;" ::: "memory");

    int rbase = warp * 32;
    int lm_row = (lane & 7) + ((lane >> 3) & 1) * 8;
    int lm_col = (lane >> 4) * 8;

    for (int c = 0; c < NCH; c++) {
        __syncthreads();
        if (c + 1 < NCH) {
            fill_async(c + 1, (c + 1) & 1);
            asm volatile("cp.async.commit_group;" ::: "memory");
            asm volatile("cp.async.wait_group 1;" ::: "memory");
        } else {
            asm volatile("cp.async.wait_group 0;" ::: "memory");
        }
        __syncthreads();
        const __half* xb = xg[c & 1];
#pragma unroll
        for (int j = 0; j < 2; j++) {
            uint32_t a[2][4];
#pragma unroll
            for (int mt = 0; mt < 2; mt++) {
                uint32_t ad = (uint32_t)__cvta_generic_to_shared(
                    &xb[(rbase + mt * 16 + lm_row) * 40 + j * 16 + lm_col]);
                asm volatile(
                    "ldmatrix.sync.aligned.m8n8.x4.shared.b16 {%0,%1,%2,%3}, [%4];"
                    : "=r"(a[mt][0]), "=r"(a[mt][1]), "=r"(a[mt][2]), "=r"(a[mt][3])
                    : "r"(ad));
            }
            int kc = c * 2 + j;
            const uint2* bp = Bpk + (size_t)(kc * NTILES + nt0) * 32 + lane;
#pragma unroll
            for (int nt = 0; nt < NT; nt++) {
                uint2 bb = bp[nt * 32];
#pragma unroll
                for (int mt = 0; mt < 2; mt++) {
                    asm volatile(
                        "mma.sync.aligned.m16n8k16.row.col.f32.f16.f16.f32 "
                        "{%0,%1,%2,%3}, {%4,%5,%6,%7}, {%8,%9}, {%0,%1,%2,%3};"
                        : "+f"(acc[mt][nt][0]), "+f"(acc[mt][nt][1]),
                          "+f"(acc[mt][nt][2]), "+f"(acc[mt][nt][3])
                        : "r"(a[mt][0]), "r"(a[mt][1]), "r"(a[mt][2]), "r"(a[mt][3]),
                          "r"(bb.x), "r"(bb.y));
                }
            }
        }
    }

#pragma unroll
    for (int mt = 0; mt < 2; mt++) {
        int row0 = rbase + mt * 16 + (lane >> 2);
#pragma unroll
        for (int hf = 0; hf < 2; hf++) {
            int row = row0 + hf * 8;
            int v = row >> 6;
            int t = row & 63;
            int n = n0 + v;
            if (n >= nverts) continue;
#pragma unroll
            for (int nt = 0; nt < NT; nt++) {
                int co = co0 + nt * 8 + (lane & 3) * 2;
                float2 bv = *(const float2*)&bias[co];
                float v0 = acc[mt][nt][hf * 2 + 0] + bv.x;
                float v1 = acc[mt][nt][hf * 2 + 1] + bv.y;
                v0 = (v0 > 0.f) ? v0 : (__expf(v0) - 1.f);
                v1 = (v1 > 0.f) ? v1 : (__expf(v1) - 1.f);
                *(__half2*)&out[((size_t)t * nverts + n) * COUT + co] = __floats2half2_rn(v0, v1);
            }
        }
    }
}

// -------------------- final conv 32->3 + actor: cp.async double-buffered --------------------
__global__ void __launch_bounds__(64)
final_kernel(const __half* __restrict__ x, const int* __restrict__ spiral,
             const float* __restrict__ WTf,  // [288][3]
             const float* __restrict__ bf,
             const float* __restrict__ actor,
             float* __restrict__ out, int nverts) {
    __shared__ float wfs[864];
    __shared__ __align__(8) __half xg[2][64 * 34];
    __shared__ int vidx[SPIRAL_S];
    int n = blockIdx.x;
    int tid = threadIdx.x;
    for (int i = tid; i < 864; i += 64) wfs[i] = WTf[i];
    if (tid < SPIRAL_S) vidx[tid] = spiral[n * SPIRAL_S + tid];
    __syncthreads();

    auto fill_async = [&](int s, int b) {
        int v = vidx[s];
#pragma unroll
        for (int i = tid; i < 1024; i += 64) {
            int tl = i >> 4;
            int u = i & 15;
            const void* g = &x[((size_t)tl * nverts + v) * 32 + u * 2];
            uint32_t d = (uint32_t)__cvta_generic_to_shared(&xg[b][tl * 34 + u * 2]);
            asm volatile("cp.async.ca.shared.global [%0], [%1], 4;" :: "r"(d), "l"(g));
        }
    };

    fill_async(0, 0);
    asm volatile("cp.async.commit_group;" ::: "memory");

    float a0 = 0.f, a1 = 0.f, a2 = 0.f;
    for (int s = 0; s < SPIRAL_S; s++) {
        __syncthreads();
        if (s + 1 < SPIRAL_S) {
            fill_async(s + 1, (s + 1) & 1);
            asm volatile("cp.async.commit_group;" ::: "memory");
            asm volatile("cp.async.wait_group 1;" ::: "memory");
        } else {
            asm volatile("cp.async.wait_group 0;" ::: "memory");
        }
        __syncthreads();
        const uint32_t* xgu = (const uint32_t*)xg[s & 1];
        int rb = tid * 17;
#pragma unroll
        for (int u = 0; u < 16; u++) {
            float2 f = __half22float2(*(const __half2*)&xgu[rb + u]);
            int kb = (s * 32 + u * 2) * 3;
            a0 += f.x * wfs[kb + 0] + f.y * wfs[kb + 3];
            a1 += f.x * wfs[kb + 1] + f.y * wfs[kb + 4];
            a2 += f.x * wfs[kb + 2] + f.y * wfs[kb + 5];
        }
    }
    size_t ob = ((size_t)tid * nverts + n) * 3;
    out[ob + 0] = a0 + bf[0] + actor[(size_t)n * 3 + 0];
    out[ob + 1] = a1 + bf[1] + actor[(size_t)n * 3 + 1];
    out[ob + 2] = a2 + bf[2] + actor[(size_t)n * 3 + 2];
}

// -------------------- host --------------------
extern "C" void kernel_launch(void* const* d_in, const int* in_sizes, int n_in_cnt,
                              void* d_out, int out_size) {
    const float* latent = (const float*)d_in[0];
    const float* actor  = (const float*)d_in[1];
    const int* sp0 = (const int*)d_in[2];
    const int* sp1 = (const int*)d_in[3];
    const int* sp2 = (const int*)d_in[4];
    const int* sp3 = (const int*)d_in[5];
    const int*   upr[4] = {(const int*)d_in[6], (const int*)d_in[9], (const int*)d_in[12], (const int*)d_in[15]};
    const int*   upc[4] = {(const int*)d_in[7], (const int*)d_in[10], (const int*)d_in[13], (const int*)d_in[16]};
    const float* upv[4] = {(const float*)d_in[8], (const float*)d_in[11], (const float*)d_in[14], (const float*)d_in[17]};
    const float* W0 = (const float*)d_in[18];
    const float* b0 = (const float*)d_in[19];
    const float* W1 = (const float*)d_in[20];
    const float* b1 = (const float*)d_in[21];
    const float* W2 = (const float*)d_in[22];
    const float* b2 = (const float*)d_in[23];
    const float* W3 = (const float*)d_in[24];
    const float* b3 = (const float*)d_in[25];
    const float* W4 = (const float*)d_in[26];
    const float* b4 = (const float*)d_in[27];
    const float* Wf = (const float*)d_in[28];
    const float* bf = (const float*)d_in[29];
    float* out = (float*)d_out;

    __half *A, *B;
    float *WT, *cval;
    int *ptr, *eid, *ccol;
    cudaGetSymbolAddress((void**)&A, g_bufA);
    cudaGetSymbolAddress((void**)&B, g_bufB);
    cudaGetSymbolAddress((void**)&WT, g_WT);
    cudaGetSymbolAddress((void**)&ptr, g_ptr);
    cudaGetSymbolAddress((void**)&eid, g_eid);
    cudaGetSymbolAddress((void**)&ccol, g_ccol);
    cudaGetSymbolAddress((void**)&cval, g_cval);

    const int LEV[5] = {5023, 1256, 314, 79, 20};
    int nnz[4] = {in_sizes[6], in_sizes[9], in_sizes[12], in_sizes[15]};

    // ---- descriptors ----
    TDesc td;
    td.W[0] = W1; td.K[0] = 1152; td.C[0] = 128;
    td.W[1] = W2; td.K[1] = 1152; td.C[1] = 64;
    td.W[2] = W3; td.K[2] = 576;  td.C[2] = 64;
    td.W[3] = W4; td.K[3] = 576;  td.C[3] = 32;
    td.W[4] = Wf; td.K[4] = 288;  td.C[4] = 3;
    int offH = 0, tot = 0;
    for (int l = 0; l < 5; l++) {
        td.offH[l] = offH;
        if (l < 4) offH += td.K[l] * td.C[l];
        tot += td.K[l] * td.C[l];
    }
    td.tot = tot;

    CsrDesc cd;
    int nzo = 0, ro = 0;
    for (int l = 0; l < 4; l++) {
        cd.rows[l] = upr[l]; cd.cols[l] = upc[l]; cd.vals[l] = upv[l];
        cd.nnz[l] = nnz[l];
        cd.nnzOff[l] = nzo; nzo += nnz[l];
        cd.nout[l] = LEV[l];
        cd.ptrOff[l] = ro + l;
        ro += LEV[l];
    }
    cd.nnzOff[4] = nzo;

    // ---- fused prologue: CSR + dense + weight pack in one launch ----
    fused_prologue<<<PRO_TOTAL_BLKS, 1024>>>(cd, ptr, eid, ccol, cval,
                                             latent, W0, b0, A, td, WT);

    const uint2* BW0 = (const uint2*)((const __half*)WT + td.offH[0]);
    const uint2* BW1 = (const uint2*)((const __half*)WT + td.offH[1]);
    const uint2* BW2 = (const uint2*)((const __half*)WT + td.offH[2]);
    const uint2* BW3 = (const uint2*)((const __half*)WT + td.offH[3]);
    const float* WFf = WT + WT_FINAL_F32_OFF;

    // ---- level 3: pool 20->79 (C=128, TCH=8), conv 128->128 (co split x4) ----
    pool_gather<128, 8><<<dim3(79, 8), 128>>>(A, B, ptr + cd.ptrOff[3], ccol, cval, 20, 79);
    conv_fp16<128, 128, 32><<<dim3(40, 1, 4), 128>>>(B, sp3, BW0, b1, A, 79);

    // ---- level 2: pool 79->314 (C=128, TCH=8), conv 128->64 (co split x2) ----
    pool_gather<128, 8><<<dim3(314, 8), 128>>>(A, B, ptr + cd.ptrOff[2], ccol, cval, 79, 314);
    conv_fp16<128, 64, 32><<<dim3(157, 1, 2), 128>>>(B, sp2, BW1, b2, A, 314);

    // ---- level 1: pool 314->1256 (C=64, TCH=16), conv 64->64 ----
    pool_gather<64, 16><<<dim3(1256, 4), 128>>>(A, B, ptr + cd.ptrOff[1], ccol, cval, 314, 1256);
    conv_fp16<64, 64, 64><<<dim3(628, 1, 1), 128>>>(B, sp1, BW2, b3, A, 1256);

    // ---- level 0: pool 1256->5023 (C=64, TCH=16), conv 64->32 ----
    pool_gather<64, 16><<<dim3(5023, 4), 128>>>(A, B, ptr + cd.ptrOff[0], ccol, cval, 1256, 5023);
    conv_fp16<64, 32, 32><<<dim3(2512, 1, 1), 128>>>(B, sp0, BW3, b4, A, 5023);

    // ---- final conv 32->3 + actor -> d_out ----
    final_kernel<<<5023, 64>>>(A, sp0, WFf, bf, actor, out, 5023);

    (void)in_sizes; (void)n_in_cnt; (void)out_size;
}